// round 2
// baseline (speedup 1.0000x reference)
#include <cuda_runtime.h>
#include <cuda_bf16.h>

// char_feats: [L=512, B=256, D=256] f32 (time-major)
// word_ids:   [B, L] i32 (per-row non-decreasing, dense 0..n-1, < 128)
// attention_mask: [B, L] i32
// out: word_feats [W=128, B, D] f32 (+ masks [W, B] f32 if out_size allows)
#define LSEQ 512
#define NW   128
#define BATCH 256
#define DDIM  256

__device__ int g_start[BATCH * (NW + 1)];
__device__ int g_validhi[BATCH];
__device__ int g_wordnum[BATCH];

// One block per batch row, 512 threads (= L).
__global__ void boundary_kernel(const int* __restrict__ word_ids,
                                const int* __restrict__ amask) {
    int b = blockIdx.x;
    int t = threadIdx.x;
    int lane = t & 31;
    int warp = t >> 5;

    __shared__ int warpsum[16];

    int id = word_ids[b * LSEQ + t];
    id = id < 0 ? 0 : (id > NW - 1 ? NW - 1 : id);  // defensive clamp

    // attention-mask sum via warp shuffles
    int m = amask[b * LSEQ + t];
    #pragma unroll
    for (int s = 16; s > 0; s >>= 1) m += __shfl_down_sync(0xffffffffu, m, s);
    if (lane == 0) warpsum[warp] = m;

    // init starts to sentinel
    if (t <= NW) g_start[b * (NW + 1) + t] = LSEQ;

    // boundary detection: neighbor via shuffle; lane 0 of warp>0 reloads t-1
    int prev = __shfl_up_sync(0xffffffffu, id, 1);
    if (lane == 0 && t > 0) {
        int p = word_ids[b * LSEQ + t - 1];
        prev = p < 0 ? 0 : (p > NW - 1 ? NW - 1 : p);
    }
    __syncthreads();

    if (t == 0) {
        g_start[b * (NW + 1) + id] = 0;
        int total = 0;
        #pragma unroll
        for (int i = 0; i < 16; ++i) total += warpsum[i];
        int char_nums = total - 2;           // drop [CLS]/[SEP]
        g_validhi[b] = 1 + char_nums;        // valid chars: l in [1, 1+char_nums)
    } else if (id != prev) {
        g_start[b * (NW + 1) + id] = t;
    }
    if (t == LSEQ - 1) g_wordnum[b] = id + 1;  // sorted -> last is max
}

// One block per (word, batch). 64 threads x float4 = D=256 floats.
// Loads issued in predicated batches of 4 -> MLP~4 per warp.
__global__ void pool_kernel(const float* __restrict__ cf,
                            float* __restrict__ out,
                            float* __restrict__ mask_out) {
    int w = blockIdx.x;
    int b = blockIdx.y;
    int t = threadIdx.x;  // 0..63

    int base = b * (NW + 1) + w;
    int s = g_start[base];
    int e = g_start[base + 1];
    int hi = g_validhi[b];

    s = s > 1 ? s : 1;
    e = e < hi ? e : hi;
    int n = e - s;  // may be <= 0 (empty / invalid word)

    const int stride4 = BATCH * DDIM / 4;  // float4 stride per l step
    const float4* p = reinterpret_cast<const float4*>(cf)
                    + (long long)s * stride4 + b * (DDIM / 4) + t;

    float4 a0 = make_float4(0.f, 0.f, 0.f, 0.f);
    float4 a1 = a0, a2 = a0, a3 = a0;

    for (int l = 0; l < n; l += 4) {
        int r = n - l;
        float4 v0, v1, v2, v3;
        // batched, predicated streaming loads (independent -> back-to-back issue)
        if (r > 0) v0 = __ldcs(p);
        if (r > 1) v1 = __ldcs(p + stride4);
        if (r > 2) v2 = __ldcs(p + 2 * stride4);
        if (r > 3) v3 = __ldcs(p + 3 * stride4);
        if (r > 0) { a0.x += v0.x; a0.y += v0.y; a0.z += v0.z; a0.w += v0.w; }
        if (r > 1) { a1.x += v1.x; a1.y += v1.y; a1.z += v1.z; a1.w += v1.w; }
        if (r > 2) { a2.x += v2.x; a2.y += v2.y; a2.z += v2.z; a2.w += v2.w; }
        if (r > 3) { a3.x += v3.x; a3.y += v3.y; a3.z += v3.z; a3.w += v3.w; }
        p += 4 * stride4;
    }

    a0.x += a1.x + a2.x + a3.x;
    a0.y += a1.y + a2.y + a3.y;
    a0.z += a1.z + a2.z + a3.z;
    a0.w += a1.w + a2.w + a3.w;

    float inv = 1.0f / (float)(n > 0 ? n : 1);
    a0.x *= inv; a0.y *= inv; a0.z *= inv; a0.w *= inv;

    float4* o = reinterpret_cast<float4*>(out)
              + (long long)(w * BATCH + b) * (DDIM / 4) + t;
    *o = a0;

    if (t == 0 && mask_out != nullptr) {
        mask_out[w * BATCH + b] = (w < g_wordnum[b]) ? 1.0f : 0.0f;
    }
}

extern "C" void kernel_launch(void* const* d_in, const int* in_sizes, int n_in,
                              void* d_out, int out_size) {
    const float* char_feats = (const float*)d_in[0];
    const int*   word_ids   = (const int*)d_in[1];
    const int*   amask      = (const int*)d_in[2];
    float* out = (float*)d_out;

    const int feats_elems = NW * BATCH * DDIM;
    float* mask_out = (out_size > feats_elems) ? (out + feats_elems) : nullptr;

    boundary_kernel<<<BATCH, LSEQ>>>(word_ids, amask);
    pool_kernel<<<dim3(NW, BATCH), 64>>>(char_feats, out, mask_out);
}

// round 4
// speedup vs baseline: 1.0010x; 1.0010x over previous
#include <cuda_runtime.h>
#include <cuda_bf16.h>

// char_feats: [L=512, B=256, D=256] f32 (time-major)
// word_ids:   [B, L] i32 (per-row non-decreasing, dense 0..n-1, < 128)
// attention_mask: [B, L] i32
// out: word_feats [W=128, B, D] f32 (+ masks [W, B] f32 if out_size allows)
#define LSEQ 512
#define NW   128
#define BATCH 256
#define DDIM  256

__device__ int g_start[BATCH * (NW + 1)];
__device__ int g_validhi[BATCH];
__device__ int g_wordnum[BATCH];

// One block per batch row, 512 threads (= L).
__global__ void boundary_kernel(const int* __restrict__ word_ids,
                                const int* __restrict__ amask) {
    int b = blockIdx.x;
    int t = threadIdx.x;
    int lane = t & 31;
    int warp = t >> 5;

    __shared__ int warpsum[16];

    int id = word_ids[b * LSEQ + t];
    id = id < 0 ? 0 : (id > NW - 1 ? NW - 1 : id);  // defensive clamp

    // attention-mask sum via warp shuffles
    int m = amask[b * LSEQ + t];
    #pragma unroll
    for (int s = 16; s > 0; s >>= 1) m += __shfl_down_sync(0xffffffffu, m, s);
    if (lane == 0) warpsum[warp] = m;

    // init starts to sentinel
    if (t <= NW) g_start[b * (NW + 1) + t] = LSEQ;

    // boundary detection: neighbor via shuffle; lane 0 of warp>0 reloads t-1
    int prev = __shfl_up_sync(0xffffffffu, id, 1);
    if (lane == 0 && t > 0) {
        int p = word_ids[b * LSEQ + t - 1];
        prev = p < 0 ? 0 : (p > NW - 1 ? NW - 1 : p);
    }
    __syncthreads();

    if (t == 0) {
        g_start[b * (NW + 1) + id] = 0;
        int total = 0;
        #pragma unroll
        for (int i = 0; i < 16; ++i) total += warpsum[i];
        int char_nums = total - 2;           // drop [CLS]/[SEP]
        g_validhi[b] = 1 + char_nums;        // valid chars: l in [1, 1+char_nums)
    } else if (id != prev) {
        g_start[b * (NW + 1) + id] = t;
    }
    if (t == LSEQ - 1) g_wordnum[b] = id + 1;  // sorted -> last is max
}

// One block per (word, batch). 64 threads x float4 = D=256 floats.
// 4/2/1 unroll ladder: independent back-to-back LDG.128s (MLP up to 4),
// single accumulator, 32-reg ceiling to keep 32 CTAs/SM resident.
__global__ void __launch_bounds__(64, 32)
pool_kernel(const float* __restrict__ cf,
            float* __restrict__ out,
            float* __restrict__ mask_out) {
    int w = blockIdx.x;
    int b = blockIdx.y;
    int t = threadIdx.x;  // 0..63

    int base = b * (NW + 1) + w;
    int s = g_start[base];
    int e = g_start[base + 1];
    int hi = g_validhi[b];

    s = s > 1 ? s : 1;
    e = e < hi ? e : hi;
    int n = e - s;  // may be <= 0 (empty / padded word)

    const int stride4 = BATCH * DDIM / 4;  // float4 stride per l step
    const float4* p = reinterpret_cast<const float4*>(cf)
                    + (long long)s * stride4 + b * (DDIM / 4) + t;

    float4 acc = make_float4(0.f, 0.f, 0.f, 0.f);

    int rem = n;
    // main: 4 independent loads in flight
    while (rem >= 4) {
        float4 v0 = __ldg(p);
        float4 v1 = __ldg(p + stride4);
        float4 v2 = __ldg(p + 2 * stride4);
        float4 v3 = __ldg(p + 3 * stride4);
        acc.x += v0.x; acc.y += v0.y; acc.z += v0.z; acc.w += v0.w;
        acc.x += v1.x; acc.y += v1.y; acc.z += v1.z; acc.w += v1.w;
        acc.x += v2.x; acc.y += v2.y; acc.z += v2.z; acc.w += v2.w;
        acc.x += v3.x; acc.y += v3.y; acc.z += v3.z; acc.w += v3.w;
        p += 4 * stride4;
        rem -= 4;
    }
    if (rem >= 2) {
        float4 v0 = __ldg(p);
        float4 v1 = __ldg(p + stride4);
        acc.x += v0.x; acc.y += v0.y; acc.z += v0.z; acc.w += v0.w;
        acc.x += v1.x; acc.y += v1.y; acc.z += v1.z; acc.w += v1.w;
        p += 2 * stride4;
        rem -= 2;
    }
    if (rem >= 1) {
        float4 v0 = __ldg(p);
        acc.x += v0.x; acc.y += v0.y; acc.z += v0.z; acc.w += v0.w;
    }

    float inv = 1.0f / (float)(n > 0 ? n : 1);
    acc.x *= inv; acc.y *= inv; acc.z *= inv; acc.w *= inv;

    float4* o = reinterpret_cast<float4*>(out)
              + (long long)(w * BATCH + b) * (DDIM / 4) + t;
    *o = acc;

    if (t == 0 && mask_out != nullptr) {
        mask_out[w * BATCH + b] = (w < g_wordnum[b]) ? 1.0f : 0.0f;
    }
}

extern "C" void kernel_launch(void* const* d_in, const int* in_sizes, int n_in,
                              void* d_out, int out_size) {
    const float* char_feats = (const float*)d_in[0];
    const int*   word_ids   = (const int*)d_in[1];
    const int*   amask      = (const int*)d_in[2];
    float* out = (float*)d_out;

    const int feats_elems = NW * BATCH * DDIM;
    float* mask_out = (out_size > feats_elems) ? (out + feats_elems) : nullptr;

    boundary_kernel<<<BATCH, LSEQ>>>(word_ids, amask);
    pool_kernel<<<dim3(NW, BATCH), 64>>>(char_feats, out, mask_out);
}